// round 3
// baseline (speedup 1.0000x reference)
#include <cuda_runtime.h>
#include <cuda_bf16.h>

// RecurrentDNNC: y_t = relu(Wd @ [W1 x_t + b1 ; y_{t-1}] + bd); out_t = sigmoid(W2 y_t + b2)
// Parallelized via chunked scan with burn-in (recurrence contracts ~0.5/step in expectation).

#define CHUNK_L 64
#define BURN_W  256

__global__ void rdnnc_scan_kernel(const float* __restrict__ x,
                                  const float* __restrict__ W1,
                                  const float* __restrict__ b1,
                                  const float* __restrict__ Wd,
                                  const float* __restrict__ bd,
                                  const float* __restrict__ W2,
                                  const float* __restrict__ b2,
                                  float* __restrict__ out,
                                  int S, int nchunks)
{
    int chunk = blockIdx.x * blockDim.x + threadIdx.x;
    if (chunk >= nchunks) return;

    // Fold fc1 into the cell:
    //   pre = A*(W1 x + b1) + B*y + bd = Cx + c + B*y
    // Wd layout (H=2, 2H=4 cols, row-major): row i = [A_i0, A_i1, B_i0, B_i1]
    const float A00 = Wd[0], A01 = Wd[1], B00 = Wd[2], B01 = Wd[3];
    const float A10 = Wd[4], A11 = Wd[5], B10 = Wd[6], B11 = Wd[7];

    float C0[4], C1[4];
#pragma unroll
    for (int j = 0; j < 4; j++) {
        // W1 is (2,4) row-major: W1[h*4 + j]
        C0[j] = A00 * W1[j] + A01 * W1[4 + j];
        C1[j] = A10 * W1[j] + A11 * W1[4 + j];
    }
    const float c0 = A00 * b1[0] + A01 * b1[1] + bd[0];
    const float c1 = A10 * b1[0] + A11 * b1[1] + bd[1];

    // W2 is (2,2) row-major; out = sigmoid(y @ W2^T + b2)
    const float w200 = W2[0], w201 = W2[1], w210 = W2[2], w211 = W2[3];
    const float ob0 = b2[0], ob1 = b2[1];

    const int t0    = chunk * CHUNK_L;
    const int tend  = min(t0 + CHUNK_L, S);
    const int start = max(0, t0 - BURN_W);   // (t0 - start) is a multiple of 8

    const float4* __restrict__ xv = (const float4*)x;

    float y0 = 0.f, y1 = 0.f;

    // ---- burn-in: converge state, no output ----
    for (int base = start; base < t0; base += 8) {
        float4 xb[8];
#pragma unroll
        for (int k = 0; k < 8; k++) xb[k] = xv[base + k];   // independent LDG.128s, front-batched
#pragma unroll
        for (int k = 0; k < 8; k++) {
            const float4 v = xb[k];
            float u0 = fmaf(C0[3], v.w, fmaf(C0[2], v.z, fmaf(C0[1], v.y, fmaf(C0[0], v.x, c0))));
            float u1 = fmaf(C1[3], v.w, fmaf(C1[2], v.z, fmaf(C1[1], v.y, fmaf(C1[0], v.x, c1))));
            float p0 = fmaf(B01, y1, fmaf(B00, y0, u0));
            float p1 = fmaf(B11, y1, fmaf(B10, y0, u1));
            y0 = fmaxf(p0, 0.f);
            y1 = fmaxf(p1, 0.f);
        }
    }

    // ---- main: produce outputs for [t0, tend) ----
    int base = t0;
    for (; base + 8 <= tend; base += 8) {
        float4 xb[8];
#pragma unroll
        for (int k = 0; k < 8; k++) xb[k] = xv[base + k];
#pragma unroll
        for (int k = 0; k < 8; k += 2) {
            float4 o;
            {
                const float4 v = xb[k];
                float u0 = fmaf(C0[3], v.w, fmaf(C0[2], v.z, fmaf(C0[1], v.y, fmaf(C0[0], v.x, c0))));
                float u1 = fmaf(C1[3], v.w, fmaf(C1[2], v.z, fmaf(C1[1], v.y, fmaf(C1[0], v.x, c1))));
                float p0 = fmaf(B01, y1, fmaf(B00, y0, u0));
                float p1 = fmaf(B11, y1, fmaf(B10, y0, u1));
                y0 = fmaxf(p0, 0.f);
                y1 = fmaxf(p1, 0.f);
                float v0 = fmaf(w201, y1, fmaf(w200, y0, ob0));
                float v1 = fmaf(w211, y1, fmaf(w210, y0, ob1));
                o.x = 1.f / (1.f + __expf(-v0));
                o.y = 1.f / (1.f + __expf(-v1));
            }
            {
                const float4 v = xb[k + 1];
                float u0 = fmaf(C0[3], v.w, fmaf(C0[2], v.z, fmaf(C0[1], v.y, fmaf(C0[0], v.x, c0))));
                float u1 = fmaf(C1[3], v.w, fmaf(C1[2], v.z, fmaf(C1[1], v.y, fmaf(C1[0], v.x, c1))));
                float p0 = fmaf(B01, y1, fmaf(B00, y0, u0));
                float p1 = fmaf(B11, y1, fmaf(B10, y0, u1));
                y0 = fmaxf(p0, 0.f);
                y1 = fmaxf(p1, 0.f);
                float v0 = fmaf(w201, y1, fmaf(w200, y0, ob0));
                float v1 = fmaf(w211, y1, fmaf(w210, y0, ob1));
                o.z = 1.f / (1.f + __expf(-v0));
                o.w = 1.f / (1.f + __expf(-v1));
            }
            // out[(base+k)*2 .. +3], (base+k) even -> 16B aligned
            ((float4*)out)[(base + k) >> 1] = o;
        }
    }
    // scalar tail (only if S % 8 != 0 for the last chunk)
    for (int t = base; t < tend; t++) {
        const float4 v = xv[t];
        float u0 = fmaf(C0[3], v.w, fmaf(C0[2], v.z, fmaf(C0[1], v.y, fmaf(C0[0], v.x, c0))));
        float u1 = fmaf(C1[3], v.w, fmaf(C1[2], v.z, fmaf(C1[1], v.y, fmaf(C1[0], v.x, c1))));
        float p0 = fmaf(B01, y1, fmaf(B00, y0, u0));
        float p1 = fmaf(B11, y1, fmaf(B10, y0, u1));
        y0 = fmaxf(p0, 0.f);
        y1 = fmaxf(p1, 0.f);
        float v0 = fmaf(w201, y1, fmaf(w200, y0, ob0));
        float v1 = fmaf(w211, y1, fmaf(w210, y0, ob1));
        out[2 * t + 0] = 1.f / (1.f + __expf(-v0));
        out[2 * t + 1] = 1.f / (1.f + __expf(-v1));
    }
}

extern "C" void kernel_launch(void* const* d_in, const int* in_sizes, int n_in,
                              void* d_out, int out_size)
{
    const float* x  = (const float*)d_in[0];   // (1, S, 4) fp32
    const float* W1 = (const float*)d_in[1];   // (2, 4)
    const float* b1 = (const float*)d_in[2];   // (2,)
    const float* Wd = (const float*)d_in[3];   // (2, 4)
    const float* bd = (const float*)d_in[4];   // (2,)
    const float* W2 = (const float*)d_in[5];   // (2, 2)
    const float* b2 = (const float*)d_in[6];   // (2,)
    float* out = (float*)d_out;                // (S, 2) fp32

    const int S = in_sizes[0] / 4;
    const int nchunks = (S + CHUNK_L - 1) / CHUNK_L;

    const int threads = 256;
    const int blocks = (nchunks + threads - 1) / threads;
    rdnnc_scan_kernel<<<blocks, threads>>>(x, W1, b1, Wd, bd, W2, b2, out, S, nchunks);
}

// round 6
// speedup vs baseline: 1.6035x; 1.6035x over previous
#include <cuda_runtime.h>
#include <cuda_bf16.h>

// RecurrentDNNC: y_t = relu(Wd @ [W1 x_t + b1 ; y_{t-1}] + bd); out_t = sigmoid(W2 y_t + b2)
// Chunked scan with burn-in; smem-transposed coalesced I/O.

#define L_CHUNK   64
#define W_BURN    128
#define TILE      8
#define THREADS   256
#define TOTAL_STEPS (W_BURN + L_CHUNK)      // 192
#define NTILES      (TOTAL_STEPS / TILE)    // 24
#define BURN_TILES  (W_BURN / TILE)         // 16
#define ROWPAD    9                          // 8 float4 payload + 1 pad (bank-conflict-free)

__global__ __launch_bounds__(THREADS, 1)
void rdnnc_scan_kernel(const float* __restrict__ x,
                       const float* __restrict__ W1,
                       const float* __restrict__ b1,
                       const float* __restrict__ Wd,
                       const float* __restrict__ bd,
                       const float* __restrict__ W2,
                       const float* __restrict__ b2,
                       float* __restrict__ out,
                       int S)
{
    __shared__ float4 sm[THREADS * ROWPAD];   // 36,864 B

    const int tid = threadIdx.x;
    const int Cb  = blockIdx.x * THREADS;     // first chunk handled by this block
    const int c   = Cb + tid;                 // this thread's chunk
    const int t0  = c * L_CHUNK;

    // Fold fc1 into the cell: pre = C*x + cst + B*y
    // Wd row i = [A_i0, A_i1, B_i0, B_i1]; W1 is (2,4) row-major.
    const float A00 = Wd[0], A01 = Wd[1], B00 = Wd[2], B01 = Wd[3];
    const float A10 = Wd[4], A11 = Wd[5], B10 = Wd[6], B11 = Wd[7];

    float C0[4], C1[4];
#pragma unroll
    for (int j = 0; j < 4; j++) {
        C0[j] = A00 * W1[j] + A01 * W1[4 + j];
        C1[j] = A10 * W1[j] + A11 * W1[4 + j];
    }
    const float c0 = A00 * b1[0] + A01 * b1[1] + bd[0];
    const float c1 = A10 * b1[0] + A11 * b1[1] + bd[1];

    const float w200 = W2[0], w201 = W2[1], w210 = W2[2], w211 = W2[3];
    const float ob0 = b2[0], ob1 = b2[1];

    const float4* __restrict__ xv = (const float4*)x;
    float4* __restrict__ ov = (float4*)out;

    float y0 = 0.f, y1 = 0.f;
    // Local step index j at which global t == 0 (exact y=0 reset for chunks 0,1;
    // negative and never taken for all other chunks).
    const int reset_j = W_BURN - t0;

#pragma unroll 1
    for (int tau = 0; tau < NTILES; ++tau) {
        const int jbase = tau * TILE;

        __syncthreads();   // previous tile fully consumed / stored

        // ---- cooperative coalesced load of this tile: 2048 float4 ----
#pragma unroll
        for (int k2 = 0; k2 < 8; ++k2) {
            int idx = tid + k2 * THREADS;     // 0..2047
            int i  = idx >> 3;                // row (chunk-local thread)
            int jj = idx & 7;                 // col (step in tile)
            int g  = (Cb + i) * L_CHUNK - W_BURN + jbase + jj;  // float4 index
            sm[i * ROWPAD + jj] = xv[max(g, 0)];
        }
        __syncthreads();

        if (tau < BURN_TILES) {
            // ---- burn-in: converge state, no output ----
#pragma unroll
            for (int jj = 0; jj < TILE; ++jj) {
                if (jbase + jj == reset_j) { y0 = 0.f; y1 = 0.f; }
                const float4 v = sm[tid * ROWPAD + jj];
                float u0 = fmaf(C0[3], v.w, fmaf(C0[2], v.z, fmaf(C0[1], v.y, fmaf(C0[0], v.x, c0))));
                float u1 = fmaf(C1[3], v.w, fmaf(C1[2], v.z, fmaf(C1[1], v.y, fmaf(C1[0], v.x, c1))));
                float p0 = fmaf(B01, y1, fmaf(B00, y0, u0));
                float p1 = fmaf(B11, y1, fmaf(B10, y0, u1));
                y0 = fmaxf(p0, 0.f);
                y1 = fmaxf(p1, 0.f);
            }
        } else {
            // ---- main: produce outputs, stage into consumed smem columns ----
#pragma unroll
            for (int jj = 0; jj < TILE; jj += 2) {
                float4 o;
                {
                    if (jbase + jj == reset_j) { y0 = 0.f; y1 = 0.f; }
                    const float4 v = sm[tid * ROWPAD + jj];
                    float u0 = fmaf(C0[3], v.w, fmaf(C0[2], v.z, fmaf(C0[1], v.y, fmaf(C0[0], v.x, c0))));
                    float u1 = fmaf(C1[3], v.w, fmaf(C1[2], v.z, fmaf(C1[1], v.y, fmaf(C1[0], v.x, c1))));
                    float p0 = fmaf(B01, y1, fmaf(B00, y0, u0));
                    float p1 = fmaf(B11, y1, fmaf(B10, y0, u1));
                    y0 = fmaxf(p0, 0.f);
                    y1 = fmaxf(p1, 0.f);
                    float v0 = fmaf(w201, y1, fmaf(w200, y0, ob0));
                    float v1 = fmaf(w211, y1, fmaf(w210, y0, ob1));
                    o.x = 1.f / (1.f + __expf(-v0));
                    o.y = 1.f / (1.f + __expf(-v1));
                }
                {
                    if (jbase + jj + 1 == reset_j) { y0 = 0.f; y1 = 0.f; }
                    const float4 v = sm[tid * ROWPAD + jj + 1];
                    float u0 = fmaf(C0[3], v.w, fmaf(C0[2], v.z, fmaf(C0[1], v.y, fmaf(C0[0], v.x, c0))));
                    float u1 = fmaf(C1[3], v.w, fmaf(C1[2], v.z, fmaf(C1[1], v.y, fmaf(C1[0], v.x, c1))));
                    float p0 = fmaf(B01, y1, fmaf(B00, y0, u0));
                    float p1 = fmaf(B11, y1, fmaf(B10, y0, u1));
                    y0 = fmaxf(p0, 0.f);
                    y1 = fmaxf(p1, 0.f);
                    float v0 = fmaf(w201, y1, fmaf(w200, y0, ob0));
                    float v1 = fmaf(w211, y1, fmaf(w210, y0, ob1));
                    o.z = 1.f / (1.f + __expf(-v0));
                    o.w = 1.f / (1.f + __expf(-v1));
                }
                // cols jj, jj+1 already consumed; col jj>>1 <= jj is safe to overwrite
                sm[tid * ROWPAD + (jj >> 1)] = o;
            }
            __syncthreads();

            // ---- cooperative coalesced store: 1024 float4 ----
            const int tm = tau - BURN_TILES;              // 0..7
#pragma unroll
            for (int k2 = 0; k2 < 4; ++k2) {
                int idx = tid + k2 * THREADS;             // 0..1023
                int i = idx >> 2;                         // row
                int k = idx & 3;                          // out float4 within tile
                ov[(Cb + i) * (L_CHUNK / 2) + tm * (TILE / 2) + k] = sm[i * ROWPAD + k];
            }
        }
    }
}

extern "C" void kernel_launch(void* const* d_in, const int* in_sizes, int n_in,
                              void* d_out, int out_size)
{
    const float* x  = (const float*)d_in[0];   // (1, S, 4) fp32
    const float* W1 = (const float*)d_in[1];   // (2, 4)
    const float* b1 = (const float*)d_in[2];   // (2,)
    const float* Wd = (const float*)d_in[3];   // (2, 4)
    const float* bd = (const float*)d_in[4];   // (2,)
    const float* W2 = (const float*)d_in[5];   // (2, 2)
    const float* b2 = (const float*)d_in[6];   // (2,)
    float* out = (float*)d_out;                // (S, 2) fp32

    const int S = in_sizes[0] / 4;             // 2^21
    const int nchunks = S / L_CHUNK;           // 32768
    const int nblocks = nchunks / THREADS;     // 128

    rdnnc_scan_kernel<<<nblocks, THREADS>>>(x, W1, b1, Wd, bd, W2, b2, out, S);
}

// round 7
// speedup vs baseline: 2.2885x; 1.4272x over previous
#include <cuda_runtime.h>
#include <cuda_bf16.h>

// RecurrentDNNC: y_t = relu(Wd @ [W1 x_t + b1 ; y_{t-1}] + bd); out_t = sigmoid(W2 y_t + b2)
// Chunked scan with burn-in; smem-transposed coalesced I/O; register-prefetch pipelined tiles.

#define L_CHUNK   32
#define W_BURN    64
#define TILE      8
#define THREADS   256
#define TOTAL_STEPS (W_BURN + L_CHUNK)      // 96
#define NTILES      (TOTAL_STEPS / TILE)    // 12
#define BURN_TILES  (W_BURN / TILE)         // 8
#define ROWPAD    9                          // 8 float4 payload + 1 pad (conflict-free per 8-lane phase)

__global__ __launch_bounds__(THREADS, 2)
void rdnnc_scan_kernel(const float* __restrict__ x,
                       const float* __restrict__ W1,
                       const float* __restrict__ b1,
                       const float* __restrict__ Wd,
                       const float* __restrict__ bd,
                       const float* __restrict__ W2,
                       const float* __restrict__ b2,
                       float* __restrict__ out,
                       int S)
{
    __shared__ float4 sm[THREADS * ROWPAD];   // 36,864 B

    const int tid = threadIdx.x;
    const int Cb  = blockIdx.x * THREADS;     // first chunk handled by this block
    const int t0  = (Cb + tid) * L_CHUNK;

    // Fold fc1 into the cell: pre = C*x + cst + B*y
    // Wd row i = [A_i0, A_i1, B_i0, B_i1]; W1 is (2,4) row-major.
    const float A00 = Wd[0], A01 = Wd[1], B00 = Wd[2], B01 = Wd[3];
    const float A10 = Wd[4], A11 = Wd[5], B10 = Wd[6], B11 = Wd[7];

    float C0[4], C1[4];
#pragma unroll
    for (int j = 0; j < 4; j++) {
        C0[j] = A00 * W1[j] + A01 * W1[4 + j];
        C1[j] = A10 * W1[j] + A11 * W1[4 + j];
    }
    const float c0 = A00 * b1[0] + A01 * b1[1] + bd[0];
    const float c1 = A10 * b1[0] + A11 * b1[1] + bd[1];

    const float w200 = W2[0], w201 = W2[1], w210 = W2[2], w211 = W2[3];
    const float ob0 = b2[0], ob1 = b2[1];

    const float4* __restrict__ xv = (const float4*)x;
    float4* __restrict__ ov = (float4*)out;

    float y0 = 0.f, y1 = 0.f;
    // Local step index at which global t == 0 (exact y=0 reset for chunks 0,1).
    const int reset_j = W_BURN - t0;

    // ---- prefetch tile 0 into registers (cooperative-coalesced pattern) ----
    float4 r[8];
#pragma unroll
    for (int k2 = 0; k2 < 8; ++k2) {
        int idx = tid + k2 * THREADS;
        int i  = idx >> 3;
        int jj = idx & 7;
        int g  = (Cb + i) * L_CHUNK - W_BURN + jj;
        r[k2] = xv[max(g, 0)];
    }

#pragma unroll 1
    for (int tau = 0; tau < NTILES; ++tau) {
        const int jbase = tau * TILE;

        __syncthreads();   // previous tile fully consumed / outputs drained

        // ---- commit prefetched tile to smem ----
#pragma unroll
        for (int k2 = 0; k2 < 8; ++k2) {
            int idx = tid + k2 * THREADS;
            sm[(idx >> 3) * ROWPAD + (idx & 7)] = r[k2];
        }

        // ---- prefetch next tile (latency hidden behind this tile's compute) ----
        if (tau + 1 < NTILES) {
#pragma unroll
            for (int k2 = 0; k2 < 8; ++k2) {
                int idx = tid + k2 * THREADS;
                int i  = idx >> 3;
                int jj = idx & 7;
                int g  = (Cb + i) * L_CHUNK - W_BURN + jbase + TILE + jj;
                r[k2] = xv[max(g, 0)];
            }
        }

        __syncthreads();   // tile tau visible in smem

        if (tau < BURN_TILES) {
            // ---- burn-in: converge state, no output ----
#pragma unroll
            for (int jj = 0; jj < TILE; ++jj) {
                if (jbase + jj == reset_j) { y0 = 0.f; y1 = 0.f; }
                const float4 v = sm[tid * ROWPAD + jj];
                float u0 = fmaf(C0[3], v.w, fmaf(C0[2], v.z, fmaf(C0[1], v.y, fmaf(C0[0], v.x, c0))));
                float u1 = fmaf(C1[3], v.w, fmaf(C1[2], v.z, fmaf(C1[1], v.y, fmaf(C1[0], v.x, c1))));
                float p0 = fmaf(B01, y1, fmaf(B00, y0, u0));
                float p1 = fmaf(B11, y1, fmaf(B10, y0, u1));
                y0 = fmaxf(p0, 0.f);
                y1 = fmaxf(p1, 0.f);
            }
        } else {
            // ---- main: produce outputs, stage into consumed smem columns ----
#pragma unroll
            for (int jj = 0; jj < TILE; jj += 2) {
                float4 o;
                {
                    if (jbase + jj == reset_j) { y0 = 0.f; y1 = 0.f; }
                    const float4 v = sm[tid * ROWPAD + jj];
                    float u0 = fmaf(C0[3], v.w, fmaf(C0[2], v.z, fmaf(C0[1], v.y, fmaf(C0[0], v.x, c0))));
                    float u1 = fmaf(C1[3], v.w, fmaf(C1[2], v.z, fmaf(C1[1], v.y, fmaf(C1[0], v.x, c1))));
                    float p0 = fmaf(B01, y1, fmaf(B00, y0, u0));
                    float p1 = fmaf(B11, y1, fmaf(B10, y0, u1));
                    y0 = fmaxf(p0, 0.f);
                    y1 = fmaxf(p1, 0.f);
                    float v0 = fmaf(w201, y1, fmaf(w200, y0, ob0));
                    float v1 = fmaf(w211, y1, fmaf(w210, y0, ob1));
                    o.x = 1.f / (1.f + __expf(-v0));
                    o.y = 1.f / (1.f + __expf(-v1));
                }
                {
                    if (jbase + jj + 1 == reset_j) { y0 = 0.f; y1 = 0.f; }
                    const float4 v = sm[tid * ROWPAD + jj + 1];
                    float u0 = fmaf(C0[3], v.w, fmaf(C0[2], v.z, fmaf(C0[1], v.y, fmaf(C0[0], v.x, c0))));
                    float u1 = fmaf(C1[3], v.w, fmaf(C1[2], v.z, fmaf(C1[1], v.y, fmaf(C1[0], v.x, c1))));
                    float p0 = fmaf(B01, y1, fmaf(B00, y0, u0));
                    float p1 = fmaf(B11, y1, fmaf(B10, y0, u1));
                    y0 = fmaxf(p0, 0.f);
                    y1 = fmaxf(p1, 0.f);
                    float v0 = fmaf(w201, y1, fmaf(w200, y0, ob0));
                    float v1 = fmaf(w211, y1, fmaf(w210, y0, ob1));
                    o.z = 1.f / (1.f + __expf(-v0));
                    o.w = 1.f / (1.f + __expf(-v1));
                }
                // cols jj, jj+1 consumed; col jj>>1 (<= jj) safe to overwrite
                sm[tid * ROWPAD + (jj >> 1)] = o;
            }
            __syncthreads();

            // ---- cooperative coalesced store: 1024 float4 ----
            const int tm = tau - BURN_TILES;              // 0..3
#pragma unroll
            for (int k2 = 0; k2 < 4; ++k2) {
                int idx = tid + k2 * THREADS;             // 0..1023
                int i = idx >> 2;                         // row
                int k = idx & 3;                          // out float4 within tile
                ov[(Cb + i) * (L_CHUNK / 2) + tm * (TILE / 2) + k] = sm[i * ROWPAD + k];
            }
        }
    }
}

extern "C" void kernel_launch(void* const* d_in, const int* in_sizes, int n_in,
                              void* d_out, int out_size)
{
    const float* x  = (const float*)d_in[0];   // (1, S, 4) fp32
    const float* W1 = (const float*)d_in[1];   // (2, 4)
    const float* b1 = (const float*)d_in[2];   // (2,)
    const float* Wd = (const float*)d_in[3];   // (2, 4)
    const float* bd = (const float*)d_in[4];   // (2,)
    const float* W2 = (const float*)d_in[5];   // (2, 2)
    const float* b2 = (const float*)d_in[6];   // (2,)
    float* out = (float*)d_out;                // (S, 2) fp32

    const int S = in_sizes[0] / 4;             // 2^21
    const int nchunks = S / L_CHUNK;           // 65536
    const int nblocks = nchunks / THREADS;     // 256

    rdnnc_scan_kernel<<<nblocks, THREADS>>>(x, W1, b1, Wd, bd, W2, b2, out, S);
}